// round 15
// baseline (speedup 1.0000x reference)
#include <cuda_runtime.h>
#include <cstdint>

// NoiseMixModule: out = mask*A + (1-mask)*B, mask from double-argsort ranks of u.
//
// R14 = R12 resubmitted (R13 was an infra failure, theory untested):
//   p1: issue 7 u loads (-> smem strip) + ALL 14 A/B float4 loads (21 LDG.128
//       in flight per warp before any compute)
//   p2: SWAR nibble rank masks, executed entirely under outstanding loads
//   p3: blend all 7 k's in registers
//   p4: 7x STG.128 in one uninterrupted write burst
//   Rationale: longer same-direction bursts cut HBM read<->write turnaround;
//   steady-state DRAM% (83.7) is the binding limit (wave/occ levers exhausted
//   in R5-R11). regs ~70 -> 3 blocks/SM, 24 warps; ~258 KB in flight/SM.

static constexpr int THREADS        = 256;
static constexpr int WARPS          = THREADS / 32;            // 8
static constexpr int ROWS_PER_WARP  = 128;
static constexpr int F4_PER_WARP    = ROWS_PER_WARP * 7 / 4;   // 224
static constexpr int ROWS_PER_BLOCK = ROWS_PER_WARP * WARPS;   // 1024
static constexpr int F4_PER_BLOCK   = F4_PER_WARP * WARPS;     // 1792

__global__ __launch_bounds__(THREADS)
void noisemix_kernel(const float4* __restrict__ A,
                     const float4* __restrict__ B,
                     const float*  __restrict__ LAM,
                     const float4* __restrict__ U,
                     float4* __restrict__ OUT)
{
    __shared__ float    su[ROWS_PER_BLOCK * 7];     // 28 KB, per-warp strips
    __shared__ uint32_t smask[ROWS_PER_BLOCK];      //  4 KB, SWAR mask words

    const int warp = threadIdx.x >> 5;
    const int lane = threadIdx.x & 31;

    float*    suw    = su    + warp * ROWS_PER_WARP * 7;
    uint32_t* smaskw = smask + warp * ROWS_PER_WARP;
    float4*   suw4   = reinterpret_cast<float4*>(suw);

    const long wbase4   = (long)blockIdx.x * F4_PER_BLOCK + warp * F4_PER_WARP;
    const long wrowbase = (long)blockIdx.x * ROWS_PER_BLOCK + warp * ROWS_PER_WARP;

    // ---- p1a: issue u loads (coalesced float4 -> smem strip) ----
#pragma unroll
    for (int k = 0; k < 7; k++) {
        suw4[k * 32 + lane] = U[wbase4 + k * 32 + lane];
    }

    // ---- p1b: issue ALL A/B loads (14 LDG.128, independent of u) ----
    float4 a[7], b[7];
#pragma unroll
    for (int k = 0; k < 7; k++) {
        const long idx4 = wbase4 + k * 32 + lane;
        a[k] = A[idx4];
        b[k] = B[idx4];
    }

    __syncwarp();

    // ---- p2: SWAR rank counts, 4 rows per lane (under outstanding loads) ----
    // stable double-argsort rank: pair (x<y): u[x] <= u[y] -> y gains a
    // predecessor, else x does. cnt_d lives in nibble d of acc.
    // mask bit d = bit3 of nibble d of (acc + (8-nz)*0x01111111).
#pragma unroll
    for (int j = 0; j < 4; j++) {
        const int row = lane + j * 32;           // stride-7 LDS: conflict-free
        float uu[7];
#pragma unroll
        for (int d = 0; d < 7; d++) uu[d] = suw[row * 7 + d];

        const float lamv = LAM[wrowbase + row];  // coalesced 4B/lane
        const int   nz   = (int)floorf(7.0f * (1.0f - lamv));

        uint32_t acc = 0;
#pragma unroll
        for (int x = 0; x < 7; x++)
#pragma unroll
            for (int y = x + 1; y < 7; y++)
                acc += (uu[x] <= uu[y]) ? (1u << (4 * y)) : (1u << (4 * x));

        smaskw[row] = acc + (uint32_t)(8 - nz) * 0x01111111u;
    }
    __syncwarp();

    // ---- p3: blend all 7 k's into output registers ----
    float4 o[7];
#pragma unroll
    for (int k = 0; k < 7; k++) {
        int le  = (k * 32 + lane) * 4;          // element idx within warp tile
        int row = le / 7;
        int d   = le - row * 7;

        uint32_t m = smaskw[row];
        o[k].x = (m >> (4 * d + 3)) & 1u ? a[k].x : b[k].x;
        d++; if (d == 7) { d = 0; row++; m = smaskw[row]; }
        o[k].y = (m >> (4 * d + 3)) & 1u ? a[k].y : b[k].y;
        d++; if (d == 7) { d = 0; row++; m = smaskw[row]; }
        o[k].z = (m >> (4 * d + 3)) & 1u ? a[k].z : b[k].z;
        d++; if (d == 7) { d = 0; row++; m = smaskw[row]; }
        o[k].w = (m >> (4 * d + 3)) & 1u ? a[k].w : b[k].w;
    }

    // ---- p4: one uninterrupted store burst (7x STG.128) ----
#pragma unroll
    for (int k = 0; k < 7; k++) {
        OUT[wbase4 + k * 32 + lane] = o[k];
    }
}

extern "C" void kernel_launch(void* const* d_in, const int* in_sizes, int n_in,
                              void* d_out, int out_size)
{
    const float4* A   = (const float4*)d_in[0];   // noise_A [B,7]
    const float4* Bp  = (const float4*)d_in[1];   // noise_B [B,7]
    const float*  LAM = (const float*)d_in[2];    // lam [B]
    const float4* U   = (const float4*)d_in[3];   // u [B,7]
    float4* OUT = (float4*)d_out;

    const int Brows  = in_sizes[2];                // 4194304
    const int blocks = Brows / ROWS_PER_BLOCK;     // 4096

    noisemix_kernel<<<blocks, THREADS>>>(A, Bp, LAM, U, OUT);
}